// round 4
// baseline (speedup 1.0000x reference)
#include <cuda_runtime.h>
#include <math.h>

#define N_LEAVES 262144
#define HID 128

// Ping-pong hidden-state buffers (static __device__ = allocation-guard safe).
__device__ float g_bufA[(size_t)N_LEAVES * HID];        // 128 MB
__device__ float g_bufB[(size_t)(N_LEAVES / 2) * HID];  //  64 MB
__device__ float g_Wcat[256 * HID];                     // vstack(W_l, W_r)
__device__ float g_bsum[HID];                           // b_l + b_r

__global__ void prep_kernel(const float* __restrict__ W_l, const float* __restrict__ b_l,
                            const float* __restrict__ W_r, const float* __restrict__ b_r) {
    int tid = threadIdx.x;
    for (int idx = tid; idx < 256 * HID; idx += blockDim.x) {
        int k = idx >> 7;
        int n = idx & 127;
        g_Wcat[idx] = (k < HID) ? W_l[k * HID + n] : W_r[(k - HID) * HID + n];
    }
    if (tid < HID) g_bsum[tid] = b_l[tid] + b_r[tid];
}

// Packed fp32 FMA: d.lo += a.lo*b.lo ; d.hi += a.hi*b.hi  (sm_10x FFMA2)
__device__ __forceinline__ void ffma2(float2& d, const float2& a, const float2& b) {
    asm("fma.rn.f32x2 %0, %1, %2, %0;"
        : "+l"(reinterpret_cast<unsigned long long&>(d))
        : "l"(reinterpret_cast<const unsigned long long&>(a)),
          "l"(reinterpret_cast<const unsigned long long&>(b)));
}

// C[M,128] = tanh(A[M,K] @ W[K,128] + bias)
// CTA tile 128 x 128, 512 threads, thread tile 8 rows x 4 cols.
// FFMA2 pairs consecutive k's: acc.lo = even-k partial, acc.hi = odd-k partial.
// W staged in smem in k-pair interleaved layout, split in 2 col-parity regions so
// inner-loop W loads are stride-1 float4 across lanes (conflict-free).
//   region j (j = (n>>1)&1), float4 index = j*(KT/2)*32 + (k>>1)*32 + (n>>2)
//   float4 content = (w[k0][c0], w[k1][c0], w[k0][c1], w[k1][c1])
template <int K>
__global__ void __launch_bounds__(512, 1)
level_gemm(const float* __restrict__ A, const float* __restrict__ W,
           const float* __restrict__ bias, float* __restrict__ C, int M) {
    constexpr int KT  = (K < 128) ? K : 128;   // K-tile
    constexpr int NST = K / KT;                // stages
    constexpr int KT4 = KT / 4;

    extern __shared__ float smem[];
    float4* sW4 = (float4*)smem;               // KT*32 float4s (two regions)
    float*  sA  = smem + KT * HID;             // 128 rows x KT
    float4* sA4 = (float4*)sA;

    const int tid = threadIdx.x;
    const int cg  = tid & 31;                  // col group: cols 4*cg .. 4*cg+3
    const int rg  = tid >> 5;                  // warp id: rows rg*8 .. rg*8+7
    const int m0  = blockIdx.x * 128;
    const int rows = (M - m0 < 128) ? (M - m0) : 128;

    float2 acc[8][4];
    #pragma unroll
    for (int r = 0; r < 8; r++)
        #pragma unroll
        for (int c = 0; c < 4; c++) acc[r][c] = make_float2(0.f, 0.f);

    for (int st = 0; st < NST; st++) {
        if (st) __syncthreads();

        // ---- stage W slice [st*KT, st*KT+KT) x 128 into interleaved layout ----
        {
            const float4* Wg = (const float4*)W;
            #pragma unroll 2
            for (int i = tid; i < KT * 32; i += 512) {
                int k = i >> 5, n4 = i & 31;
                float4 v = Wg[(size_t)(st * KT + k) * 32 + n4];
                int base0 = ((k >> 1) * 32 + n4) * 4 + (k & 1);      // region 0
                int base1 = (KT / 2) * 128 + base0;                  // region 1
                smem[base0]     = v.x;
                smem[base0 + 2] = v.y;
                smem[base1]     = v.z;
                smem[base1 + 2] = v.w;
            }
        }
        // ---- stage A tile: rows x KT (k slice) ----
        {
            const float* Ab = A + (size_t)m0 * K + st * KT;
            for (int i = tid; i < rows * KT4; i += 512) {
                int r = i / KT4, kk = i % KT4;
                sA4[r * KT4 + kk] = ((const float4*)(Ab + (size_t)r * K))[kk];
            }
        }
        __syncthreads();

        // ---- compute ----
        const float4* myA = sA4 + rg * 8 * KT4;
        #pragma unroll
        for (int k4 = 0; k4 < KT4; k4++) {
            float4 a[8];
            #pragma unroll
            for (int r = 0; r < 8; r++) a[r] = myA[r * KT4 + k4];   // warp broadcast
            #pragma unroll
            for (int h = 0; h < 2; h++) {                           // k2 = k4*2 + h
                float4 w0 = sW4[(k4 * 2 + h) * 32 + cg];            // cols 4cg,4cg+1
                float4 w1 = sW4[(KT / 2) * 32 + (k4 * 2 + h) * 32 + cg]; // cols +2,+3
                #pragma unroll
                for (int r = 0; r < 8; r++) {
                    float2 ap = h ? make_float2(a[r].z, a[r].w)
                                  : make_float2(a[r].x, a[r].y);
                    ffma2(acc[r][0], ap, make_float2(w0.x, w0.y));
                    ffma2(acc[r][1], ap, make_float2(w0.z, w0.w));
                    ffma2(acc[r][2], ap, make_float2(w1.x, w1.y));
                    ffma2(acc[r][3], ap, make_float2(w1.z, w1.w));
                }
            }
        }
    }

    // ---- epilogue: combine halves, bias, tanh, store ----
    float4 bv = ((const float4*)bias)[cg];
    #pragma unroll
    for (int r = 0; r < 8; r++) {
        int row = rg * 8 + r;
        if (row < rows) {
            float4 o;
            o.x = tanhf(acc[r][0].x + acc[r][0].y + bv.x);
            o.y = tanhf(acc[r][1].x + acc[r][1].y + bv.y);
            o.z = tanhf(acc[r][2].x + acc[r][2].y + bv.z);
            o.w = tanhf(acc[r][3].x + acc[r][3].y + bv.w);
            ((float4*)C)[(size_t)(m0 + row) * 32 + cg] = o;
        }
    }
}

extern "C" void kernel_launch(void* const* d_in, const int* in_sizes, int n_in,
                              void* d_out, int out_size) {
    const float* leaf_x = (const float*)d_in[0];
    const float* W_in   = (const float*)d_in[1];
    const float* b_in   = (const float*)d_in[2];
    const float* W_l    = (const float*)d_in[3];
    const float* b_l    = (const float*)d_in[4];
    const float* W_r    = (const float*)d_in[5];
    const float* b_r    = (const float*)d_in[6];

    void *pA, *pB, *pW, *pb;
    cudaGetSymbolAddress(&pA, g_bufA);
    cudaGetSymbolAddress(&pB, g_bufB);
    cudaGetSymbolAddress(&pW, g_Wcat);
    cudaGetSymbolAddress(&pb, g_bsum);
    float* bufA = (float*)pA;
    float* bufB = (float*)pB;
    float* Wcat = (float*)pW;
    float* bsum = (float*)pb;

    const int smem_leaf  = 2 * 64  * HID * (int)sizeof(float);   //  64 KB
    const int smem_level = 2 * 128 * HID * (int)sizeof(float);   // 128 KB
    cudaFuncSetAttribute(level_gemm<64>,  cudaFuncAttributeMaxDynamicSharedMemorySize, smem_leaf);
    cudaFuncSetAttribute(level_gemm<256>, cudaFuncAttributeMaxDynamicSharedMemorySize, smem_level);

    prep_kernel<<<1, 256>>>(W_l, b_l, W_r, b_r);

    // Leaf: H0 = tanh(leaf_x @ W_in + b_in)
    level_gemm<64><<<N_LEAVES / 128, 512, smem_leaf>>>(leaf_x, W_in, b_in, bufA, N_LEAVES);

    // 18 internal levels: reshape(H,[M/2,256]) @ vstack(W_l,W_r) + (b_l+b_r)
    float* cur = bufA;
    int M = N_LEAVES;
    for (int lvl = 0; lvl < 18; lvl++) {
        int Mo = M >> 1;
        float* out = (lvl == 17) ? (float*)d_out : ((lvl & 1) ? bufA : bufB);
        level_gemm<256><<<(Mo + 127) / 128, 512, smem_level>>>(cur, Wcat, bsum, out, Mo);
        cur = out;
        M = Mo;
    }
}

// round 6
// speedup vs baseline: 1.3075x; 1.3075x over previous
#include <cuda_runtime.h>
#include <cuda_bf16.h>
#include <math.h>
#include <stdint.h>

#define HID 128
#define NLV 262144

// ---------------- device buffers (static = allocation-guard safe) ----------------
// Paired-row bf16 hi/lo operand arrays for the next level: A[m][k], k in [0,256).
__device__ __nv_bfloat16 g_Ahi[(size_t)131072 * 256];   // 64 MB
__device__ __nv_bfloat16 g_Alo[(size_t)131072 * 256];   // 64 MB
__device__ __nv_bfloat16 g_Bhi[(size_t)65536 * 256];    // 32 MB
__device__ __nv_bfloat16 g_Blo[(size_t)65536 * 256];    // 32 MB
// K-major split weights (same layout as the originals: W[k][n]).
__device__ __nv_bfloat16 g_WLhi[256 * 128], g_WLlo[256 * 128];  // vstack(W_l,W_r)
__device__ __nv_bfloat16 g_WIhi[64 * 128],  g_WIlo[64 * 128];   // W_in
__device__ float g_bsum[128];                                   // b_l + b_r

// ---------------- helpers ----------------
// pack two fp32 -> bf16x2 (a -> low half, b -> high half)
__device__ __forceinline__ uint32_t f2bf2(float a, float b) {
    uint32_t r;
    asm("cvt.rn.bf16x2.f32 %0, %1, %2;" : "=r"(r) : "f"(b), "f"(a));
    return r;
}
__device__ __forceinline__ float bf_lo(uint32_t p) { return __uint_as_float(p << 16); }
__device__ __forceinline__ float bf_hi(uint32_t p) { return __uint_as_float(p & 0xFFFF0000u); }

__device__ __forceinline__ void ldm_x4(uint32_t* r, uint32_t addr) {
    asm volatile("ldmatrix.sync.aligned.m8n8.x4.shared.b16 {%0,%1,%2,%3}, [%4];"
                 : "=r"(r[0]), "=r"(r[1]), "=r"(r[2]), "=r"(r[3]) : "r"(addr));
}
__device__ __forceinline__ void ldm_x4_t(uint32_t* r, uint32_t addr) {
    asm volatile("ldmatrix.sync.aligned.m8n8.x4.trans.shared.b16 {%0,%1,%2,%3}, [%4];"
                 : "=r"(r[0]), "=r"(r[1]), "=r"(r[2]), "=r"(r[3]) : "r"(addr));
}
__device__ __forceinline__ void mma_bf16(float* c, const uint32_t* a, const uint32_t* b) {
    asm volatile("mma.sync.aligned.m16n8k16.row.col.f32.bf16.bf16.f32 "
                 "{%0,%1,%2,%3}, {%4,%5,%6,%7}, {%8,%9}, {%0,%1,%2,%3};"
                 : "+f"(c[0]), "+f"(c[1]), "+f"(c[2]), "+f"(c[3])
                 : "r"(a[0]), "r"(a[1]), "r"(a[2]), "r"(a[3]), "r"(b[0]), "r"(b[1]));
}

// Swizzles: A rows are 128B, W rows are 256B. Both permute 16B chunks so that
// 8 consecutive rows (one ldmatrix phase) hit distinct chunks -> conflict-free.
#define SWZA(o) ((o) ^ ((((uint32_t)(o)) >> 3) & 0x70))
#define SWZW(o) ((o) ^ (((((uint32_t)(o)) >> 8) & 7) << 4))

// ---------------- smem layout ----------------
#define SM_BIAS 0
#define SM_AHI  1024
#define SM_ALO  (1024 + 16384)
#define SM_WHI  (1024 + 32768)
#define SM_WLO  (1024 + 49152)
#define SMEM_BYTES (1024 + 65536)

// ---------------- prep: split weights hi/lo (K-major, no transpose), bias sum ----
__global__ void prep_kernel(const float* __restrict__ W_in,
                            const float* __restrict__ W_l, const float* __restrict__ b_l,
                            const float* __restrict__ W_r, const float* __restrict__ b_r) {
    int t = blockIdx.x * blockDim.x + threadIdx.x;
    int stride = gridDim.x * blockDim.x;
    for (int idx = t; idx < 256 * 128; idx += stride) {
        float w = (idx < 128 * 128) ? W_l[idx] : W_r[idx - 128 * 128];
        __nv_bfloat16 h = __float2bfloat16(w);
        g_WLhi[idx] = h;
        g_WLlo[idx] = __float2bfloat16(w - __bfloat162float(h));
    }
    for (int idx = t; idx < 64 * 128; idx += stride) {
        float w = W_in[idx];
        __nv_bfloat16 h = __float2bfloat16(w);
        g_WIhi[idx] = h;
        g_WIlo[idx] = __float2bfloat16(w - __bfloat162float(h));
    }
    if (t < 128) g_bsum[t] = b_l[t] + b_r[t];
}

// ---------------- level kernel ----------------
// H[Mo,128] = tanh(A[Mo,K] @ W[K,128] + bias), 3-pass bf16-split via mma.sync.
// Writes next level's paired-row operands: nX[gm>>1][col + 128*(gm&1)].
// LEAF: A = fp32 leafX[Mo,64] split on the fly; else A = (Ahi,Alo) bf16 [Mo,K].
template <int K, bool LEAF>
__global__ void __launch_bounds__(256)
rnn_level(const float* __restrict__ leafX,
          const __nv_bfloat16* __restrict__ Ahi, const __nv_bfloat16* __restrict__ Alo,
          const __nv_bfloat16* __restrict__ Whi, const __nv_bfloat16* __restrict__ Wlo,
          const float* __restrict__ bias,
          __nv_bfloat16* __restrict__ nHi, __nv_bfloat16* __restrict__ nLo,
          float* __restrict__ outF, int Mo) {
    extern __shared__ char smem[];
    const uint32_t sb = (uint32_t)__cvta_generic_to_shared(smem);
    const int tid = threadIdx.x, l = tid & 31, wid = tid >> 5;
    const int wm = wid & 3, wn = wid >> 2;          // warp grid 4 (m) x 2 (n)
    const int m0 = blockIdx.x * 128;

    if (tid < 128) ((float*)(smem + SM_BIAS))[tid] = bias[tid];

    float acc[2][8][4];
    #pragma unroll
    for (int mt = 0; mt < 2; mt++)
        #pragma unroll
        for (int nt = 0; nt < 8; nt++)
            #pragma unroll
            for (int q = 0; q < 4; q++) acc[mt][nt][q] = 0.f;

    constexpr int NST = K / 64;
    for (int st = 0; st < NST; st++) {
        if (st) __syncthreads();
        // ---- stage W slice [64 k x 128 n] hi/lo (K-major, 256B rows) ----
        for (int i = tid; i < 64 * 16; i += 256) {
            int krow = i >> 4, ch = i & 15;
            uint32_t off = SWZW((uint32_t)(krow * 256 + ch * 16));
            size_t gi = (size_t)(st * 64 + krow) * 128 + ch * 8;
            *(uint4*)(smem + SM_WHI + off) = *(const uint4*)(Whi + gi);
            *(uint4*)(smem + SM_WLO + off) = *(const uint4*)(Wlo + gi);
        }
        // ---- stage A slice [128 rows x 64 k] hi/lo (128B rows) ----
        if (LEAF) {
            for (int i = tid; i < 128 * 8; i += 256) {
                int r = i >> 3, kg = i & 7;
                const float* src = leafX + (size_t)(m0 + r) * 64 + kg * 8;
                float4 f0 = *(const float4*)src;
                float4 f1 = *(const float4*)(src + 4);
                float xs[8] = {f0.x, f0.y, f0.z, f0.w, f1.x, f1.y, f1.z, f1.w};
                uint32_t hp[4], lp[4];
                #pragma unroll
                for (int j = 0; j < 4; j++) {
                    hp[j] = f2bf2(xs[2 * j], xs[2 * j + 1]);
                    lp[j] = f2bf2(xs[2 * j] - bf_lo(hp[j]), xs[2 * j + 1] - bf_hi(hp[j]));
                }
                uint32_t off = SWZA((uint32_t)(r * 128 + kg * 16));
                *(uint4*)(smem + SM_AHI + off) = make_uint4(hp[0], hp[1], hp[2], hp[3]);
                *(uint4*)(smem + SM_ALO + off) = make_uint4(lp[0], lp[1], lp[2], lp[3]);
            }
        } else {
            for (int i = tid; i < 128 * 8; i += 256) {
                int r = i >> 3, kg = i & 7;
                uint32_t off = SWZA((uint32_t)(r * 128 + kg * 16));
                size_t gi = (size_t)(m0 + r) * K + st * 64 + kg * 8;
                *(uint4*)(smem + SM_AHI + off) = *(const uint4*)(Ahi + gi);
                *(uint4*)(smem + SM_ALO + off) = *(const uint4*)(Alo + gi);
            }
        }
        __syncthreads();

        // ---- 3 passes over this K stage: Ahi*Whi, Ahi*Wlo, Alo*Whi ----
        #pragma unroll
        for (int p = 0; p < 3; p++) {
            const uint32_t aB = sb + ((p == 2) ? SM_ALO : SM_AHI);
            const uint32_t wB = sb + ((p == 1) ? SM_WLO : SM_WHI);
            #pragma unroll
            for (int ks = 0; ks < 4; ks++) {       // 16-wide k steps in 64
                uint32_t a[2][4], b[8][2];
                #pragma unroll
                for (int mt = 0; mt < 2; mt++) {
                    int row = wm * 32 + mt * 16 + ((l >> 3) & 1) * 8 + (l & 7);
                    int kb  = ks * 32 + (l >> 4) * 16;
                    ldm_x4(a[mt], aB + SWZA((uint32_t)(row * 128 + kb)));
                }
                #pragma unroll
                for (int ntp = 0; ntp < 4; ntp++) {
                    int krow = ks * 16 + ((l >> 3) & 1) * 8 + (l & 7);
                    int nb   = (wn * 64 + ntp * 16 + (l >> 4) * 8) * 2;
                    uint32_t t4[4];
                    ldm_x4_t(t4, wB + SWZW((uint32_t)(krow * 256 + nb)));
                    b[ntp * 2][0]     = t4[0];
                    b[ntp * 2][1]     = t4[1];
                    b[ntp * 2 + 1][0] = t4[2];
                    b[ntp * 2 + 1][1] = t4[3];
                }
                #pragma unroll
                for (int mt = 0; mt < 2; mt++)
                    #pragma unroll
                    for (int nt = 0; nt < 8; nt++)
                        mma_bf16(acc[mt][nt], a[mt], b[nt]);
            }
        }
    }

    // ---- epilogue: bias + tanh + hi/lo split-store in paired-row layout ----
    const float* sBias = (const float*)(smem + SM_BIAS);
    #pragma unroll
    for (int mt = 0; mt < 2; mt++) {
        #pragma unroll
        for (int nt = 0; nt < 8; nt++) {
            int c = wn * 64 + nt * 8 + (l & 3) * 2;
            #pragma unroll
            for (int half = 0; half < 2; half++) {
                int gm = m0 + wm * 32 + mt * 16 + (l >> 2) + half * 8;
                if (gm < Mo) {
                    float x0 = acc[mt][nt][half * 2]     + sBias[c];
                    float x1 = acc[mt][nt][half * 2 + 1] + sBias[c + 1];
                    float t0 = tanhf(x0), t1 = tanhf(x1);
                    uint32_t hp = f2bf2(t0, t1);
                    uint32_t lp = f2bf2(t0 - bf_lo(hp), t1 - bf_hi(hp));
                    size_t base = (size_t)(gm >> 1) * 256 + (size_t)((gm & 1) * 128 + c);
                    *(uint32_t*)(nHi + base) = hp;
                    *(uint32_t*)(nLo + base) = lp;
                    if (outF) {
                        outF[(size_t)gm * HID + c]     = t0;
                        outF[(size_t)gm * HID + c + 1] = t1;
                    }
                }
            }
        }
    }
}

// ---------------- host ----------------
extern "C" void kernel_launch(void* const* d_in, const int* in_sizes, int n_in,
                              void* d_out, int out_size) {
    const float* leaf_x = (const float*)d_in[0];
    const float* W_in   = (const float*)d_in[1];
    const float* b_in   = (const float*)d_in[2];
    const float* W_l    = (const float*)d_in[3];
    const float* b_l    = (const float*)d_in[4];
    const float* W_r    = (const float*)d_in[5];
    const float* b_r    = (const float*)d_in[6];

    void *pAh, *pAl, *pBh, *pBl, *pWLh, *pWLl, *pWIh, *pWIl, *pbs;
    cudaGetSymbolAddress(&pAh, g_Ahi);    cudaGetSymbolAddress(&pAl, g_Alo);
    cudaGetSymbolAddress(&pBh, g_Bhi);    cudaGetSymbolAddress(&pBl, g_Blo);
    cudaGetSymbolAddress(&pWLh, g_WLhi);  cudaGetSymbolAddress(&pWLl, g_WLlo);
    cudaGetSymbolAddress(&pWIh, g_WIhi);  cudaGetSymbolAddress(&pWIl, g_WIlo);
    cudaGetSymbolAddress(&pbs, g_bsum);
    __nv_bfloat16 *Ah = (__nv_bfloat16*)pAh, *Al = (__nv_bfloat16*)pAl;
    __nv_bfloat16 *Bh = (__nv_bfloat16*)pBh, *Bl = (__nv_bfloat16*)pBl;
    __nv_bfloat16 *WLh = (__nv_bfloat16*)pWLh, *WLl = (__nv_bfloat16*)pWLl;
    __nv_bfloat16 *WIh = (__nv_bfloat16*)pWIh, *WIl = (__nv_bfloat16*)pWIl;
    float* bsum = (float*)pbs;

    cudaFuncSetAttribute(rnn_level<64, true>,   cudaFuncAttributeMaxDynamicSharedMemorySize, SMEM_BYTES);
    cudaFuncSetAttribute(rnn_level<256, false>, cudaFuncAttributeMaxDynamicSharedMemorySize, SMEM_BYTES);

    prep_kernel<<<64, 256>>>(W_in, W_l, b_l, W_r, b_r);

    // Leaf: H0[262144,128] -> writes level-1 operand pair into (Ah, Al).
    rnn_level<64, true><<<NLV / 128, 256, SMEM_BYTES>>>(
        leaf_x, nullptr, nullptr, WIh, WIl, b_in, Ah, Al, nullptr, NLV);

    // 18 internal levels, ping-pong operand pairs.
    __nv_bfloat16 *curH = Ah, *curL = Al;
    int M = NLV / 2;
    for (int lvl = 0; lvl < 18; lvl++) {
        __nv_bfloat16* nxtH = (curH == Ah) ? Bh : Ah;
        __nv_bfloat16* nxtL = (curL == Al) ? Bl : Al;
        float* of = (lvl == 17) ? (float*)d_out : nullptr;
        rnn_level<256, false><<<(M + 127) / 128, 256, SMEM_BYTES>>>(
            nullptr, curH, curL, WLh, WLl, bsum, nxtH, nxtL, of, M);
        curH = nxtH; curL = nxtL;
        M >>= 1;
    }
}